// round 1
// baseline (speedup 1.0000x reference)
#include <cuda_runtime.h>

// SegmenterTensorFlow: windowed framing + overlap-add reconstruction.
// B=8, N=4194304, seg=1024, hop=512 -> NSEG=8191, out_len=N.
//
// Outputs concatenated in d_out:
//   X     : [B, NSEG, SEG]  = 67,100,672 floats
//   x_rec : [B, N]          = 33,554,432 floats
//
// Since hop = seg/2, each sample n lies in exactly two segments:
//   s0 = n>>9 with j = m = n&511          (invalid when s0 == NSEG, i.e. last 512 samples)
//   s0-1      with j = m + 512            (invalid when s0 == 0, i.e. first 512 samples)
// so x_rec[b,n] = x[b,n] * (v0*aw[m]*sw[m] + v1*aw[m+512]*sw[m+512]).

#define BB   8
#define NN   4194304
#define SEG  1024
#define HOP  512
#define NSEG 8191

__global__ __launch_bounds__(256)
void seg_olap_kernel(const float* __restrict__ x,
                     const float* __restrict__ aw,
                     const float* __restrict__ sw,
                     float* __restrict__ Xout,
                     float* __restrict__ rec)
{
    long long t = (long long)blockIdx.x * blockDim.x + threadIdx.x;
    long long i = t << 2;                       // element index into [B*N]
    if (i >= (long long)BB * NN) return;

    int b = (int)(i >> 22);                     // N = 2^22
    int n = (int)(i & (NN - 1));
    int m = n & (HOP - 1);                      // uniform mod-512 phase (vec-aligned)
    int s0 = n >> 9;

    const bool v0 = (s0 < NSEG);                // segment s0, offset m
    const bool v1 = (s0 >= 1);                  // segment s0-1, offset m+512

    float4 xv  = *reinterpret_cast<const float4*>(x + i);
    float4 awl = *reinterpret_cast<const float4*>(aw + m);
    float4 awh = *reinterpret_cast<const float4*>(aw + m + HOP);
    float4 swl = *reinterpret_cast<const float4*>(sw + m);
    float4 swh = *reinterpret_cast<const float4*>(sw + m + HOP);

    // X writes (coalesced: consecutive n -> consecutive j within a segment row)
    if (v0) {
        float4 lo;
        lo.x = xv.x * awl.x; lo.y = xv.y * awl.y;
        lo.z = xv.z * awl.z; lo.w = xv.w * awl.w;
        size_t off = ((size_t)b * NSEG + s0) * SEG + m;
        *reinterpret_cast<float4*>(Xout + off) = lo;
    }
    if (v1) {
        float4 hi;
        hi.x = xv.x * awh.x; hi.y = xv.y * awh.y;
        hi.z = xv.z * awh.z; hi.w = xv.w * awh.w;
        size_t off = ((size_t)b * NSEG + (s0 - 1)) * SEG + (m + HOP);
        *reinterpret_cast<float4*>(Xout + off) = hi;
    }

    // overlap-add collapses to pointwise weight
    float w0 = v0 ? 1.0f : 0.0f;
    float w1 = v1 ? 1.0f : 0.0f;
    float4 r;
    r.x = xv.x * (w0 * awl.x * swl.x + w1 * awh.x * swh.x);
    r.y = xv.y * (w0 * awl.y * swl.y + w1 * awh.y * swh.y);
    r.z = xv.z * (w0 * awl.z * swl.z + w1 * awh.z * swh.z);
    r.w = xv.w * (w0 * awl.w * swl.w + w1 * awh.w * swh.w);
    *reinterpret_cast<float4*>(rec + i) = r;
}

extern "C" void kernel_launch(void* const* d_in, const int* in_sizes, int n_in,
                              void* d_out, int out_size)
{
    const float* x  = (const float*)d_in[0];
    const float* aw = (const float*)d_in[1];
    const float* sw = (const float*)d_in[2];

    float* Xout = (float*)d_out;
    float* rec  = Xout + (size_t)BB * NSEG * SEG;

    const long long total_vec4 = ((long long)BB * NN) / 4;   // 8,388,608
    const int threads = 256;
    const int blocks = (int)((total_vec4 + threads - 1) / threads);

    seg_olap_kernel<<<blocks, threads>>>(x, aw, sw, Xout, rec);
}